// round 5
// baseline (speedup 1.0000x reference)
#include <cuda_runtime.h>
#include <cstdint>

#define NN 100000
#define FF 128
#define EE 1600000
#define GG 512          // 4*FF gates
#define NOUTD 64
#define KARY 8
#define NPERMS 4
#define PARTITIONABLE 1 // JAX jax_threefry_partitionable default (>=0.4.36). Flip to 0 if rel_err is O(1).

// ------------------------- scratch (__device__ globals; no allocation) -------------------------
__device__ float d_XW[NN * (size_t)GG];     // node_feat @ w_ih^T  (100k x 512)
__device__ float d_h[NN * (size_t)FF];
__device__ float d_c[NN * (size_t)FF];
__device__ float d_hneigh[NN * (size_t)FF];
__device__ float d_WtIH[FF * GG];           // transposed w_ih: [k][j]
__device__ float d_WtHH[FF * GG];           // transposed w_hh: [k][j]
__device__ float d_bcat[GG];                // b_ih + b_hh
__device__ int d_deg[NN];
__device__ int d_off[NN + 1];
__device__ int d_cur[NN];
__device__ int d_csr[EE];
__device__ unsigned d_ubits[EE];            // (threefry_bits >> 9), 23 bits
__device__ int d_nbrT[KARY * NN];           // step-major neighbor ids
__device__ int d_len[NN];

// ------------------------- threefry2x32-20 (bit-exact vs JAX) -------------------------
__device__ __forceinline__ uint32_t rotl32(uint32_t v, int d) { return (v << d) | (v >> (32 - d)); }

__device__ __forceinline__ void threefry2x32(uint32_t k0, uint32_t k1,
                                             uint32_t x0, uint32_t x1,
                                             uint32_t& o0, uint32_t& o1) {
    uint32_t ks2 = k0 ^ k1 ^ 0x1BD11BDAu;
    x0 += k0; x1 += k1;
#define TF_R(r) { x0 += x1; x1 = rotl32(x1, r); x1 ^= x0; }
    TF_R(13) TF_R(15) TF_R(26) TF_R(6)   x0 += k1;  x1 += ks2 + 1u;
    TF_R(17) TF_R(29) TF_R(16) TF_R(24)  x0 += ks2; x1 += k0 + 2u;
    TF_R(13) TF_R(15) TF_R(26) TF_R(6)   x0 += k0;  x1 += k1 + 3u;
    TF_R(17) TF_R(29) TF_R(16) TF_R(24)  x0 += k1;  x1 += ks2 + 4u;
    TF_R(13) TF_R(15) TF_R(26) TF_R(6)   x0 += ks2; x1 += k0 + 5u;
#undef TF_R
    o0 = x0; o1 = x1;
}

// ------------------------- activation helpers -------------------------
__device__ __forceinline__ float sigf(float x) {
    return __fdividef(1.f, 1.f + __expf(-x));
}
__device__ __forceinline__ float tanhf_fast(float x) {
    float ax = fabsf(x);
    float e = __expf(-2.f * ax);
    float t = (1.f - e) * __fdividef(1.f, 1.f + e);
    return copysignf(t, x);
}

// ------------------------- setup kernels -------------------------
__global__ void zero_pre_kernel() {
    for (int i = blockIdx.x * blockDim.x + threadIdx.x; i < NN * FF; i += gridDim.x * blockDim.x) {
        d_hneigh[i] = 0.f;
        if (i < NN) d_deg[i] = 0;
    }
}

__global__ void deg_kernel(const int* __restrict__ adj) {
    int e = blockIdx.x * blockDim.x + threadIdx.x;
    if (e >= EE) return;
    atomicAdd(&d_deg[adj[2 * e]], 1);
}

__global__ void scan_kernel() {  // single block, 1024 threads: exclusive scan of deg -> off, cur
    __shared__ int sh[32];
    int tid = threadIdx.x;
    unsigned lane = tid & 31, wid = tid >> 5;
    int carry = 0;
    for (int base = 0; base < NN; base += 1024) {
        int i = base + tid;
        int v = (i < NN) ? d_deg[i] : 0;
        int x = v;
        #pragma unroll
        for (int s = 1; s < 32; s <<= 1) {
            int y = __shfl_up_sync(0xFFFFFFFFu, x, s);
            if (lane >= s) x += y;
        }
        if (lane == 31) sh[wid] = x;
        __syncthreads();
        if (wid == 0) {
            int y2 = sh[lane];
            #pragma unroll
            for (int s = 1; s < 32; s <<= 1) {
                int z = __shfl_up_sync(0xFFFFFFFFu, y2, s);
                if (lane >= s) y2 += z;
            }
            sh[lane] = y2;
        }
        __syncthreads();
        int wpre = (wid == 0) ? 0 : sh[wid - 1];
        int incl = wpre + x;
        if (i < NN) { d_off[i] = carry + incl - v; d_cur[i] = carry + incl - v; }
        int tot = sh[31];
        __syncthreads();
        carry += tot;
    }
    if (tid == 0) d_off[NN] = carry;
}

__global__ void fill_kernel(const int* __restrict__ adj) {
    int e = blockIdx.x * blockDim.x + threadIdx.x;
    if (e >= EE) return;
    int s = adj[2 * e];
    int pos = atomicAdd(&d_cur[s], 1);
    d_csr[pos] = e;
}

__global__ void trans_kernel(const float* __restrict__ w_ih, const float* __restrict__ w_hh,
                             const float* __restrict__ b_ih, const float* __restrict__ b_hh) {
    int idx = blockIdx.x * blockDim.x + threadIdx.x;
    if (idx < FF * GG) {
        int j = idx / FF, k = idx % FF;     // w is (512,128) row-major
        d_WtIH[k * GG + j] = w_ih[idx];
        d_WtHH[k * GG + j] = w_hh[idx];
    }
    if (idx < GG) d_bcat[idx] = b_ih[idx] + b_hh[idx];
}

// ------------------------- per-perm kernels -------------------------
__global__ void rng_kernel(int p) {
    int e = blockIdx.x * blockDim.x + threadIdx.x;
    if (e >= EE) return;
    // perm_key = fold_in(key(42), p) = threefry((0,42),(0,p))
    uint32_t ka, kb;
    threefry2x32(0u, 42u, 0u, (uint32_t)p, ka, kb);
    uint32_t o0, o1, bits;
#if PARTITIONABLE
    threefry2x32(ka, kb, 0u, (uint32_t)e, o0, o1);
    bits = o0 ^ o1;
#else
    const int H = EE / 2;
    if (e < H) { threefry2x32(ka, kb, (uint32_t)e, (uint32_t)(e + H), o0, o1); bits = o0; }
    else       { threefry2x32(ka, kb, (uint32_t)(e - H), (uint32_t)e, o0, o1); bits = o1; }
#endif
    d_ubits[e] = bits >> 9;   // monotone with the uniform float; ties broken by edge idx
}

__global__ void select_kernel(const int* __restrict__ adj) {
    int n = blockIdx.x * blockDim.x + threadIdx.x;
    if (n >= NN) return;
    int off = d_off[n];
    int d = d_deg[n];
    unsigned long long k8[KARY];
    int dst8[KARY];
    #pragma unroll
    for (int i = 0; i < KARY; i++) { k8[i] = ~0ull; dst8[i] = 0; }
    for (int ii = 0; ii < d; ii++) {
        int e = d_csr[off + ii];
        unsigned long long key = ((unsigned long long)d_ubits[e] << 21) | (unsigned)e;
        int dv = adj[2 * e + 1];
        if (key < k8[KARY - 1]) {
            #pragma unroll
            for (int s = 0; s < KARY; s++) {
                if (key < k8[s]) {
                    unsigned long long tk = k8[s]; k8[s] = key; key = tk;
                    int td = dst8[s]; dst8[s] = dv; dv = td;
                }
            }
        }
    }
    int ln = d < KARY ? d : KARY;
    d_len[n] = ln;
    #pragma unroll
    for (int t = 0; t < KARY; t++) d_nbrT[t * NN + n] = (t < ln) ? dst8[t] : 0;
}

__global__ void zero_hc_kernel() {
    for (int i = blockIdx.x * blockDim.x + threadIdx.x; i < NN * FF; i += gridDim.x * blockDim.x) {
        d_h[i] = 0.f; d_c[i] = 0.f;
    }
}

__global__ void accum_kernel() {
    for (int i = blockIdx.x * blockDim.x + threadIdx.x; i < NN * FF; i += gridDim.x * blockDim.x)
        d_hneigh[i] += d_c[i];
}

// ------------------------- GEMM: XW = node_feat @ w_ih^T  (M=NN, N=512, K=128) -------------------------
__global__ __launch_bounds__(512, 1) void xw_kernel(const float* __restrict__ nf) {
    __shared__ __align__(16) float As[8 * 68];
    __shared__ __align__(16) float Bs[8 * 512];
    int tid = threadIdx.x;
    int base = blockIdx.x * 64;
    int ns = tid & 15, js = tid >> 4;    // ns: 4-node slot, js: 4-col slot within 128
    float acc[4][16];
    #pragma unroll
    for (int i = 0; i < 4; i++)
        #pragma unroll
        for (int jv = 0; jv < 16; jv++) acc[i][jv] = 0.f;

    for (int kb = 0; kb < FF; kb += 8) {
        int n_l = tid >> 3, kk = tid & 7;
        int n = base + n_l;
        As[kk * 68 + n_l] = (n < NN) ? nf[(size_t)n * FF + kb + kk] : 0.f;
        const float4* Bg = (const float4*)(d_WtIH + kb * GG);
        ((float4*)Bs)[tid] = Bg[tid];
        ((float4*)Bs)[tid + 512] = Bg[tid + 512];
        __syncthreads();
        #pragma unroll
        for (int k2 = 0; k2 < 8; ++k2) {
            float4 a = *(const float4*)&As[k2 * 68 + ns * 4];
            float av[4] = {a.x, a.y, a.z, a.w};
            #pragma unroll
            for (int q = 0; q < 4; ++q) {
                float4 b = *(const float4*)&Bs[k2 * 512 + q * 128 + js * 4];
                float bv[4] = {b.x, b.y, b.z, b.w};
                #pragma unroll
                for (int i = 0; i < 4; i++)
                    #pragma unroll
                    for (int v = 0; v < 4; v++)
                        acc[i][q * 4 + v] = fmaf(av[i], bv[v], acc[i][q * 4 + v]);
            }
        }
        __syncthreads();
    }
    #pragma unroll
    for (int i = 0; i < 4; i++) {
        int n = base + ns * 4 + i;
        if (n >= NN) continue;
        #pragma unroll
        for (int q = 0; q < 4; q++) {
            float4 r = make_float4(acc[i][q * 4 + 0], acc[i][q * 4 + 1], acc[i][q * 4 + 2], acc[i][q * 4 + 3]);
            *(float4*)&d_XW[(size_t)n * GG + q * 128 + js * 4] = r;
        }
    }
}

// --------------- LSTM step: gates = XW[nbr] + bcat + h @ w_hh^T; fused cell update ---------------
__global__ __launch_bounds__(512, 1) void lstm_step_kernel(int t) {
    __shared__ __align__(16) float As[8 * 68];
    __shared__ __align__(16) float Bs[8 * 512];
    int tid = threadIdx.x;
    int base = blockIdx.x * 64;
    int ns = tid & 15, js = tid >> 4;
    float acc[4][16];

    // init: gather XW row of neighbor + combined bias (thread owns cols q*128 + js*4 + v, q=0..3)
    float4 bc[4];
    #pragma unroll
    for (int q = 0; q < 4; q++) bc[q] = *(const float4*)&d_bcat[q * 128 + js * 4];
    #pragma unroll
    for (int i = 0; i < 4; i++) {
        int n = base + ns * 4 + i;
        int nb = (n < NN) ? d_nbrT[t * NN + n] : 0;
        const float4* xr = (const float4*)&d_XW[(size_t)nb * GG];
        #pragma unroll
        for (int q = 0; q < 4; q++) {
            float4 x4 = xr[q * 32 + js];
            acc[i][q * 4 + 0] = x4.x + bc[q].x;
            acc[i][q * 4 + 1] = x4.y + bc[q].y;
            acc[i][q * 4 + 2] = x4.z + bc[q].z;
            acc[i][q * 4 + 3] = x4.w + bc[q].w;
        }
    }

    // K-loop: h-part only (K=128)
    for (int kb = 0; kb < FF; kb += 8) {
        int n_l = tid >> 3, kk = tid & 7;
        int n = base + n_l;
        As[kk * 68 + n_l] = (n < NN) ? d_h[(size_t)n * FF + kb + kk] : 0.f;
        const float4* Bg = (const float4*)(d_WtHH + kb * GG);
        ((float4*)Bs)[tid] = Bg[tid];
        ((float4*)Bs)[tid + 512] = Bg[tid + 512];
        __syncthreads();
        #pragma unroll
        for (int k2 = 0; k2 < 8; ++k2) {
            float4 a = *(const float4*)&As[k2 * 68 + ns * 4];
            float av[4] = {a.x, a.y, a.z, a.w};
            #pragma unroll
            for (int q = 0; q < 4; ++q) {
                float4 b = *(const float4*)&Bs[k2 * 512 + q * 128 + js * 4];
                float bv[4] = {b.x, b.y, b.z, b.w};
                #pragma unroll
                for (int i = 0; i < 4; i++)
                    #pragma unroll
                    for (int v = 0; v < 4; v++)
                        acc[i][q * 4 + v] = fmaf(av[i], bv[v], acc[i][q * 4 + v]);
            }
        }
        __syncthreads();
    }

    // cell epilogue: gate groups i/f/g/o are q=0..3, feature index f = js*4+v (thread-local)
    #pragma unroll
    for (int i = 0; i < 4; i++) {
        int n = base + ns * 4 + i;
        if (n >= NN) continue;
        if (t >= d_len[n]) continue;           // state frozen past sequence length
        size_t off = (size_t)n * FF + js * 4;
        float4 co = *(const float4*)&d_c[off];
        float cv[4] = {co.x, co.y, co.z, co.w};
        float cn[4], hn[4];
        #pragma unroll
        for (int v = 0; v < 4; v++) {
            float iv = sigf(acc[i][0 * 4 + v]);
            float fv = sigf(acc[i][1 * 4 + v]);
            float gv = tanhf_fast(acc[i][2 * 4 + v]);
            float ov = sigf(acc[i][3 * 4 + v]);
            float cc = fmaf(fv, cv[v], iv * gv);
            cn[v] = cc;
            hn[v] = ov * tanhf_fast(cc);
        }
        *(float4*)&d_c[off] = make_float4(cn[0], cn[1], cn[2], cn[3]);
        *(float4*)&d_h[off] = make_float4(hn[0], hn[1], hn[2], hn[3]);
    }
}

// ------------------------- output layer -------------------------
__global__ __launch_bounds__(512) void out_kernel(const float* __restrict__ nf,
                                                  const float* __restrict__ w,
                                                  const float* __restrict__ bias,
                                                  float* __restrict__ out) {
    int base = blockIdx.x * 64;
    int o = threadIdx.x & 63;
    int ng = threadIdx.x >> 6;   // 0..7
    for (int g = 0; g < 8; ++g) {
        int n = base + g * 8 + ng;
        if (n >= NN) continue;
        float z = bias[o];
        const float* nfr = nf + (size_t)n * FF;
        const float* hr = d_hneigh + (size_t)n * FF;
        #pragma unroll 4
        for (int k = 0; k < FF; k++) z = fmaf(nfr[k], w[k * NOUTD + o], z);
        #pragma unroll 4
        for (int k = 0; k < FF; k++) z = fmaf(0.25f * hr[k], w[(FF + k) * NOUTD + o], z);
        out[(size_t)n * NOUTD + o] = 1.f / (1.f + __expf(-z));
    }
}

// ------------------------- launch -------------------------
extern "C" void kernel_launch(void* const* d_in, const int* in_sizes, int n_in,
                              void* d_out, int out_size) {
    const float* node_feat = (const float*)d_in[0];
    const int*   adj       = (const int*)d_in[1];
    const float* w_ih      = (const float*)d_in[2];
    const float* w_hh      = (const float*)d_in[3];
    const float* b_ih      = (const float*)d_in[4];
    const float* b_hh      = (const float*)d_in[5];
    const float* weight    = (const float*)d_in[6];
    const float* bias      = (const float*)d_in[7];
    float* out = (float*)d_out;

    const int EB = (EE + 255) / 256;        // 6250
    const int NB64 = (NN + 63) / 64;        // 1563

    zero_pre_kernel<<<2048, 256>>>();
    deg_kernel<<<EB, 256>>>(adj);
    scan_kernel<<<1, 1024>>>();
    fill_kernel<<<EB, 256>>>(adj);
    trans_kernel<<<(FF * GG + 511) / 512, 512>>>(w_ih, w_hh, b_ih, b_hh);
    xw_kernel<<<NB64, 512>>>(node_feat);

    for (int p = 0; p < NPERMS; p++) {
        rng_kernel<<<EB, 256>>>(p);
        select_kernel<<<(NN + 255) / 256, 256>>>(adj);
        zero_hc_kernel<<<2048, 256>>>();
        for (int t = 0; t < KARY; t++) lstm_step_kernel<<<NB64, 512>>>(t);
        accum_kernel<<<2048, 256>>>();
    }
    out_kernel<<<NB64, 512>>>(node_feat, weight, bias, out);
}